// round 8
// baseline (speedup 1.0000x reference)
#include <cuda_runtime.h>

#define N_POS   1024
#define BDIM    512
#define SPLIT   9
#define NBLK    (64 * SPLIT)   // 576 = single wave at 4 blocks/SM
#define KTOP    10
#define NWARP   (BDIM / 32)    // 16
#define LSIZE   1088           // list capacity (1024 + 64 pad), float2 entries

__device__ float    g_partial[NBLK];
__device__ int      g_count[NBLK];
__device__ unsigned g_ticket;     // zero-init; reset to 0 by the last block each launch
__device__ float    g_disc[N_POS];   // 1/log2(p+2), filled by init kernel

__constant__ float c_idcg[11] = {
    0.0f, 1.0f, 1.6309297535714574f, 2.1309297535714574f,
    2.5616063116448505f, 2.9484591188793920f, 3.3046663059874144f,
    3.6379996393207477f, 3.9534645161064764f, 4.2544945117704580f,
    4.5435593380883460f
};

// Tiny init kernel: discount table (deterministic, rewritten every launch)
__global__ void disc_init()
{
    int p = blockIdx.x * blockDim.x + threadIdx.x;
    if (p < N_POS) g_disc[p] = 1.0f / __log2f((float)p + 2.0f);
}

__global__ __launch_bounds__(BDIM, 4) void lambdarank_fused(
    const float* __restrict__ scores, const int* __restrict__ rels,
    float* __restrict__ out)
{
    __shared__ float2 relSD[LSIZE];   // (e^{-si}, disc_i), zero-padded tail
    __shared__ float2 nonSD[LSIZE];   // (e^{+sj}, disc_j), zero-padded tail
    __shared__ int    sh_cntR[NWARP];
    __shared__ int    sh_baseR[NWARP], sh_baseN[NWARP];
    __shared__ int    sh_tot[2];
    __shared__ float  red_f[NWARP];
    __shared__ int    red_i[NWARP];
    __shared__ bool   s_last;

    const int b    = blockIdx.x / SPLIT;
    const int s    = blockIdx.x - b * SPLIT;
    const int t    = threadIdx.x;
    const int lane = t & 31;
    const int wid  = t >> 5;
    const unsigned lt_mask = (1u << lane) - 1u;

    // ---- Parallel deterministic stable compaction (16 warps, 64 pos each) ----
    unsigned masks[2];
    float    sc[2], dc[2];
    {
        int cr = 0;
        #pragma unroll
        for (int it = 0; it < 2; it++) {
            int p = (wid << 6) + (it << 5) + lane;
            sc[it] = scores[b * N_POS + p];
            dc[it] = g_disc[p];                       // coalesced LDG, L1/L2-hot
            int r  = rels[b * N_POS + p];
            unsigned m = __ballot_sync(0xffffffffu, r != 0);
            masks[it] = m;
            cr += __popc(m);
        }
        if (lane == 0) sh_cntR[wid] = cr;
    }
    __syncthreads();
    if (t == 0) {
        int aR = 0, aN = 0;
        #pragma unroll
        for (int w = 0; w < NWARP; w++) {
            sh_baseR[w] = aR; sh_baseN[w] = aN;
            aR += sh_cntR[w]; aN += 64 - sh_cntR[w];
        }
        sh_tot[0] = aR; sh_tot[1] = aN;
    }
    __syncthreads();

    const int nrel = sh_tot[0];
    const int nnon = sh_tot[1];

    {
        int rb = sh_baseR[wid], nb = sh_baseN[wid];
        #pragma unroll
        for (int it = 0; it < 2; it++) {
            unsigned m = masks[it];
            bool hit = (m >> lane) & 1u;
            float E  = __expf(hit ? -sc[it] : sc[it]);
            float2 v = make_float2(E, dc[it]);
            int preR = __popc(m & lt_mask);
            if (hit) relSD[rb + preR]          = v;
            else     nonSD[nb + (lane - preR)] = v;
            rb += __popc(m);
            nb += 32 - __popc(m);
        }
    }

    // Zero-fill tails (disjoint from scatter region): E=0 => exact 0 contribution
    for (int idx = nrel + t; idx < LSIZE; idx += BDIM)
        relSD[idx] = make_float2(0.0f, 0.0f);
    for (int idx = nnon + t; idx < LSIZE; idx += BDIM)
        nonSD[idx] = make_float2(0.0f, 0.0f);
    __syncthreads();

    float thread_sum = 0.0f;
    int   blk_count  = 0;

    if (nrel > 0 && nnon > 0) {
        const float idcg = c_idcg[(nrel < KTOP) ? nrel : KTOP];
        const float norm = 0.69314718055994531f / (idcg + 1e-8f);  // ln2/(idcg+eps)

        // Contiguous j-chunk per block, multiple of 8
        const int chunk = (((nnon + SPLIT - 1) / SPLIT) + 7) & ~7;
        const int j0    = s * chunk;
        int cntj  = nnon - j0;
        cntj  = (cntj < 0) ? 0 : ((cntj > chunk) ? chunk : cntj);
        blk_count = nrel * cntj;

        // trips rounded to multiple of 4; overread lands in zero-pad
        const int trips = (cntj + 3) & ~3;
        const float2* nj = &nonSD[j0];

        if (trips > 0) {
            #pragma unroll
            for (int ibase = 0; ibase < N_POS; ibase += BDIM) {   // 2 iterations
                if (ibase >= nrel) break;
                if (ibase + (wid << 5) >= nrel) continue;   // whole-warp tail skip
                const float2 rv = relSD[ibase + t];         // zero-pad covers overhang
                const float Ei = rv.x, di = rv.y;

                float a0 = 0.0f, a1 = 0.0f, a2 = 0.0f, a3 = 0.0f;
                for (int k = 0; k < trips; k += 4) {
                    const float2 n0 = nj[k];
                    const float2 n1 = nj[k + 1];
                    const float2 n2 = nj[k + 2];
                    const float2 n3 = nj[k + 3];
                    a0 = fmaf(fabsf(di - n0.y), __log2f(fmaf(n0.x, Ei, 1.0f)), a0);
                    a1 = fmaf(fabsf(di - n1.y), __log2f(fmaf(n1.x, Ei, 1.0f)), a1);
                    a2 = fmaf(fabsf(di - n2.y), __log2f(fmaf(n2.x, Ei, 1.0f)), a2);
                    a3 = fmaf(fabsf(di - n3.y), __log2f(fmaf(n3.x, Ei, 1.0f)), a3);
                }
                thread_sum += (a0 + a1) + (a2 + a3);
            }
            thread_sum *= norm;
        }
    }

    // ---- Deterministic block reduction (16 warps) ----
    {
        float ws = thread_sum;
        #pragma unroll
        for (int o = 16; o > 0; o >>= 1) ws += __shfl_down_sync(0xffffffffu, ws, o);
        if (lane == 0) red_f[wid] = ws;
        __syncthreads();
        if (wid == 0) {
            float v2 = (lane < NWARP) ? red_f[lane] : 0.0f;
            #pragma unroll
            for (int o = 8; o > 0; o >>= 1) v2 += __shfl_down_sync(0xffffffffu, v2, o);
            if (lane == 0) {
                g_partial[blockIdx.x] = v2;
                g_count[blockIdx.x]   = blk_count;
            }
        }
    }

    // ---- Fused finalize: last block reduces all partials in fixed order ----
    __threadfence();
    if (t == 0)
        s_last = (atomicAdd(&g_ticket, 1u) == (unsigned)(NBLK - 1));
    __syncthreads();

    if (s_last) {
        float fs = 0.0f;
        int   cs = 0;
        for (int idx = t; idx < NBLK; idx += BDIM) {
            fs += g_partial[idx];
            cs += g_count[idx];
        }
        #pragma unroll
        for (int o = 16; o > 0; o >>= 1) {
            fs += __shfl_down_sync(0xffffffffu, fs, o);
            cs += __shfl_down_sync(0xffffffffu, cs, o);
        }
        if (lane == 0) { red_f[wid] = fs; red_i[wid] = cs; }
        __syncthreads();
        if (t == 0) {
            float st = 0.0f; int ct = 0;
            #pragma unroll
            for (int w = 0; w < NWARP; w++) { st += red_f[w]; ct += red_i[w]; }
            out[0] = (ct > 0) ? (st / (float)ct) : 0.0f;
            g_ticket = 0;   // reset for next graph replay
        }
    }
}

extern "C" void kernel_launch(void* const* d_in, const int* in_sizes, int n_in,
                              void* d_out, int out_size)
{
    const float* scores = (const float*)d_in[0];
    const int*   rels   = (const int*)d_in[1];
    (void)in_sizes; (void)n_in; (void)out_size;

    disc_init<<<4, 256>>>();
    lambdarank_fused<<<NBLK, BDIM>>>(scores, rels, (float*)d_out);
}

// round 9
// speedup vs baseline: 1.1404x; 1.1404x over previous
#include <cuda_runtime.h>

#define N_POS   1024
#define BDIM    512
#define SPLIT   4
#define NBLK    (64 * SPLIT)   // 256
#define KTOP    10
#define NWARP   (BDIM / 32)    // 16
#define LSIZE   1088           // list capacity (1024 + 64 pad), float2 entries

__device__ float    g_partial[NBLK];
__device__ int      g_count[NBLK];
__device__ unsigned g_ticket;   // zero-init; reset to 0 by the last block each launch

__constant__ float c_idcg[11] = {
    0.0f, 1.0f, 1.6309297535714574f, 2.1309297535714574f,
    2.5616063116448505f, 2.9484591188793920f, 3.3046663059874144f,
    3.6379996393207477f, 3.9534645161064764f, 4.2544945117704580f,
    4.5435593380883460f
};

// e^x on FMA/ALU pipes only (no MUFU). |x| <= ~8 here (scores ~N(0,1)).
__device__ __forceinline__ float exp_fma(float x)
{
    float y = x * 1.4426950408889634f;        // x * log2(e)
    float n = rintf(y);
    float f = y - n;                           // [-0.5, 0.5]
    float p = 0.0096181291f;                   // 2^f Taylor deg-4
    p = fmaf(p, f, 0.0555041087f);
    p = fmaf(p, f, 0.2402265070f);
    p = fmaf(p, f, 0.6931471806f);
    p = fmaf(p, f, 1.0f);
    return __int_as_float(__float_as_int(p) + (((int)n) << 23));
}

// log2(x) for x in [2, 1026), FMA/ALU pipes only. abs err ~1e-5.
__device__ __forceinline__ float log2_fma(float x)
{
    int   i = __float_as_int(x);
    int   e = (i >> 23) - 127;
    float m = __int_as_float((i & 0x007FFFFF) | 0x3F800000);   // [1,2)
    if (m > 1.4142135f) { m *= 0.5f; e += 1; }                 // m in [0.707,1.414)
    float t = m - 1.0f;                                        // (-0.293, 0.414]
    float p = -0.1442695041f;                                  // log2(1+t) Taylor deg-10
    p = fmaf(p, t,  0.1602994490f);
    p = fmaf(p, t, -0.1803368802f);
    p = fmaf(p, t,  0.2060992917f);
    p = fmaf(p, t, -0.2404491735f);
    p = fmaf(p, t,  0.2885390082f);
    p = fmaf(p, t, -0.3606737602f);
    p = fmaf(p, t,  0.4808983470f);
    p = fmaf(p, t, -0.7213475204f);
    p = fmaf(p, t,  1.4426950409f);
    return fmaf(p, t, (float)e);
}

// 1/x for x in [1, ~11], no MUFU: magic-constant seed + 3 Newton steps.
__device__ __forceinline__ float rcp_fma(float x)
{
    float y = __int_as_float(0x7EF311C2 - __float_as_int(x));
    y = y * fmaf(-x, y, 2.0f);
    y = y * fmaf(-x, y, 2.0f);
    y = y * fmaf(-x, y, 2.0f);
    return y;
}

__global__ __launch_bounds__(BDIM, 2) void lambdarank_fused(
    const float* __restrict__ scores, const int* __restrict__ rels,
    float* __restrict__ out)
{
    __shared__ float2 relSD[LSIZE];   // (e^{-si}, disc_i), zero-padded tail
    __shared__ float2 nonSD[LSIZE];   // (e^{+sj}, disc_j), zero-padded tail
    __shared__ int    sh_cntR[NWARP];
    __shared__ int    sh_baseR[NWARP], sh_baseN[NWARP];
    __shared__ int    sh_tot[2];
    __shared__ float  red_f[NWARP];
    __shared__ int    red_i[NWARP];
    __shared__ bool   s_last;

    const int b    = blockIdx.x >> 2;          // SPLIT = 4
    const int s    = blockIdx.x & (SPLIT - 1);
    const int t    = threadIdx.x;
    const int lane = t & 31;
    const int wid  = t >> 5;
    const unsigned lt_mask = (1u << lane) - 1u;

    // ---- Parallel deterministic stable compaction (16 warps, 64 pos each) ----
    unsigned masks[2];
    float    sc[2];
    {
        int cr = 0;
        #pragma unroll
        for (int it = 0; it < 2; it++) {
            int p = (wid << 6) + (it << 5) + lane;
            sc[it] = scores[b * N_POS + p];
            int r  = rels[b * N_POS + p];
            unsigned m = __ballot_sync(0xffffffffu, r != 0);
            masks[it] = m;
            cr += __popc(m);
        }
        if (lane == 0) sh_cntR[wid] = cr;
    }
    __syncthreads();
    if (t == 0) {
        int aR = 0, aN = 0;
        #pragma unroll
        for (int w = 0; w < NWARP; w++) {
            sh_baseR[w] = aR; sh_baseN[w] = aN;
            aR += sh_cntR[w]; aN += 64 - sh_cntR[w];
        }
        sh_tot[0] = aR; sh_tot[1] = aN;
    }
    __syncthreads();

    const int nrel = sh_tot[0];
    const int nnon = sh_tot[1];

    {
        int rb = sh_baseR[wid], nb = sh_baseN[wid];
        #pragma unroll
        for (int it = 0; it < 2; it++) {
            int p = (wid << 6) + (it << 5) + lane;
            unsigned m = masks[it];
            bool hit = (m >> lane) & 1u;
            float E  = exp_fma(hit ? -sc[it] : sc[it]);        // 0 MUFU
            float d  = rcp_fma(log2_fma((float)p + 2.0f));     // 0 MUFU
            float2 v = make_float2(E, d);
            int preR = __popc(m & lt_mask);
            if (hit) relSD[rb + preR]          = v;
            else     nonSD[nb + (lane - preR)] = v;
            rb += __popc(m);
            nb += 32 - __popc(m);
        }
    }

    // Zero-fill tails: E=0 entries contribute exactly 0 in the pair loop
    for (int idx = nrel + t; idx < LSIZE; idx += BDIM)
        relSD[idx] = make_float2(0.0f, 0.0f);
    for (int idx = nnon + t; idx < LSIZE; idx += BDIM)
        nonSD[idx] = make_float2(0.0f, 0.0f);
    __syncthreads();

    float thread_sum = 0.0f;
    int   blk_count  = 0;

    if (nrel > 0 && nnon > 0) {
        const float idcg = c_idcg[(nrel < KTOP) ? nrel : KTOP];
        const float norm = 0.69314718055994531f / (idcg + 1e-8f);  // ln2/(idcg+eps)

        const int chunk = (((nnon + SPLIT - 1) >> 2) + 7) & ~7;
        const int j0    = s * chunk;
        int cntj  = nnon - j0;
        cntj  = (cntj < 0) ? 0 : ((cntj > chunk) ? chunk : cntj);
        blk_count = nrel * cntj;

        const int trips = (cntj + 3) & ~3;       // overread lands in zero-pad
        const float2* nj = &nonSD[j0];

        if (trips > 0) {
            for (int ibase = 0; ibase < nrel; ibase += BDIM) {
                if (ibase + (wid << 5) >= nrel) continue;   // whole-warp tail skip
                const float2 rv = relSD[ibase + t];         // zero-pad covers overhang
                const float Ei = rv.x, di = rv.y;

                float a0 = 0.0f, a1 = 0.0f, a2 = 0.0f, a3 = 0.0f;
                for (int k = 0; k < trips; k += 4) {
                    const float2 n0 = nj[k];
                    const float2 n1 = nj[k + 1];
                    const float2 n2 = nj[k + 2];
                    const float2 n3 = nj[k + 3];
                    a0 = fmaf(fabsf(di - n0.y), __log2f(fmaf(n0.x, Ei, 1.0f)), a0);
                    a1 = fmaf(fabsf(di - n1.y), __log2f(fmaf(n1.x, Ei, 1.0f)), a1);
                    a2 = fmaf(fabsf(di - n2.y), __log2f(fmaf(n2.x, Ei, 1.0f)), a2);
                    a3 = fmaf(fabsf(di - n3.y), __log2f(fmaf(n3.x, Ei, 1.0f)), a3);
                }
                thread_sum += (a0 + a1) + (a2 + a3);
            }
            thread_sum *= norm;
        }
    }

    // ---- Deterministic block reduction (16 warps) ----
    {
        float ws = thread_sum;
        #pragma unroll
        for (int o = 16; o > 0; o >>= 1) ws += __shfl_down_sync(0xffffffffu, ws, o);
        if (lane == 0) red_f[wid] = ws;
        __syncthreads();
        if (wid == 0) {
            float v2 = (lane < NWARP) ? red_f[lane] : 0.0f;
            #pragma unroll
            for (int o = 8; o > 0; o >>= 1) v2 += __shfl_down_sync(0xffffffffu, v2, o);
            if (lane == 0) {
                g_partial[blockIdx.x] = v2;
                g_count[blockIdx.x]   = blk_count;
            }
        }
    }

    // ---- Fused finalize: last block reduces all partials in fixed order ----
    __threadfence();
    if (t == 0)
        s_last = (atomicAdd(&g_ticket, 1u) == (unsigned)(NBLK - 1));
    __syncthreads();

    if (s_last) {
        float fs = 0.0f;
        int   cs = 0;
        if (t < NBLK) {                      // NBLK=256 < BDIM=512
            fs = g_partial[t];
            cs = g_count[t];
        }
        #pragma unroll
        for (int o = 16; o > 0; o >>= 1) {
            fs += __shfl_down_sync(0xffffffffu, fs, o);
            cs += __shfl_down_sync(0xffffffffu, cs, o);
        }
        if (lane == 0) { red_f[wid] = fs; red_i[wid] = cs; }
        __syncthreads();
        if (t == 0) {
            float st = 0.0f; int ct = 0;
            #pragma unroll
            for (int w = 0; w < NWARP; w++) { st += red_f[w]; ct += red_i[w]; }
            out[0] = (ct > 0) ? (st / (float)ct) : 0.0f;
            g_ticket = 0;   // reset for next graph replay
        }
    }
}

extern "C" void kernel_launch(void* const* d_in, const int* in_sizes, int n_in,
                              void* d_out, int out_size)
{
    const float* scores = (const float*)d_in[0];
    const int*   rels   = (const int*)d_in[1];
    (void)in_sizes; (void)n_in; (void)out_size;

    lambdarank_fused<<<NBLK, BDIM>>>(scores, rels, (float*)d_out);
}